// round 4
// baseline (speedup 1.0000x reference)
#include <cuda_runtime.h>
#include <math.h>

#define B_  4
#define S_  1024
#define E_  1024
#define H_  16
#define D_  64

// Scratch (static device globals: allocation-guard safe)
__device__ float g_qkv[(size_t)B_ * S_ * 3 * E_];   // [B*S, 3E] = [4096, 3072]
__device__ float g_att[(size_t)B_ * S_ * E_];       // [B*S, E]  = [4096, 1024]

// ---------------------------------------------------------------------------
// Tiled SGEMM with bias: C[M,N] = A[M,K] @ B[K,N] + bias[N]
// BM=128, BN=128, BK=16, 256 threads, 8x8 per-thread microtile.
// Double-buffered smem pipeline: prefetch slab k+1 into registers while
// computing slab k; one __syncthreads() per slab.
// Requires M%128==0, N%128==0, K%16==0 (true for all shapes here).
// ---------------------------------------------------------------------------
__global__ __launch_bounds__(256) void sgemm_bias(
    const float* __restrict__ A, const float* __restrict__ Bm,
    const float* __restrict__ bias, float* __restrict__ C,
    int M, int N, int K)
{
    __shared__ float As[2][16][132];   // transposed A tile, padded
    __shared__ float Bs[2][16][128];

    const int tid = threadIdx.x;
    const int tx  = tid & 15;          // 16 thread-cols
    const int ty  = tid >> 4;          // 16 thread-rows
    const int m0  = blockIdx.y * 128;
    const int n0  = blockIdx.x * 128;

    // per-thread load coordinates (2 float4 each for A and B per slab)
    int ar[2], ac[2], br[2], bc[2];
#pragma unroll
    for (int it = 0; it < 2; ++it) {
        int id = tid + it * 256;
        ar[it] = id >> 2;  ac[it] = (id & 3)  << 2;
        br[it] = id >> 5;  bc[it] = (id & 31) << 2;
    }

    float acc[8][8];
#pragma unroll
    for (int i = 0; i < 8; ++i)
#pragma unroll
        for (int j = 0; j < 8; ++j) acc[i][j] = 0.f;

    // prologue: slab 0 -> buffer 0
#pragma unroll
    for (int it = 0; it < 2; ++it) {
        float4 va = *(const float4*)(A + (size_t)(m0 + ar[it]) * K + ac[it]);
        As[0][ac[it] + 0][ar[it]] = va.x;
        As[0][ac[it] + 1][ar[it]] = va.y;
        As[0][ac[it] + 2][ar[it]] = va.z;
        As[0][ac[it] + 3][ar[it]] = va.w;
        float4 vb = *(const float4*)(Bm + (size_t)br[it] * N + n0 + bc[it]);
        *(float4*)&Bs[0][br[it]][bc[it]] = vb;
    }
    __syncthreads();

    int buf = 0;
    for (int k0 = 0; k0 < K; k0 += 16) {
        const bool has_next = (k0 + 16) < K;
        float4 pva[2], pvb[2];
        if (has_next) {                 // issue prefetch loads early
#pragma unroll
            for (int it = 0; it < 2; ++it) {
                pva[it] = *(const float4*)(A + (size_t)(m0 + ar[it]) * K + k0 + 16 + ac[it]);
                pvb[it] = *(const float4*)(Bm + (size_t)(k0 + 16 + br[it]) * N + n0 + bc[it]);
            }
        }

#pragma unroll
        for (int k = 0; k < 16; ++k) {
            float ra[8], rb[8];
            *(float4*)&ra[0] = *(const float4*)&As[buf][k][ty * 8];
            *(float4*)&ra[4] = *(const float4*)&As[buf][k][ty * 8 + 4];
            *(float4*)&rb[0] = *(const float4*)&Bs[buf][k][tx * 8];
            *(float4*)&rb[4] = *(const float4*)&Bs[buf][k][tx * 8 + 4];
#pragma unroll
            for (int i = 0; i < 8; ++i)
#pragma unroll
                for (int j = 0; j < 8; ++j)
                    acc[i][j] += ra[i] * rb[j];
        }

        if (has_next) {                 // drain prefetch into the other buffer
            int nb = buf ^ 1;
#pragma unroll
            for (int it = 0; it < 2; ++it) {
                As[nb][ac[it] + 0][ar[it]] = pva[it].x;
                As[nb][ac[it] + 1][ar[it]] = pva[it].y;
                As[nb][ac[it] + 2][ar[it]] = pva[it].z;
                As[nb][ac[it] + 3][ar[it]] = pva[it].w;
                *(float4*)&Bs[nb][br[it]][bc[it]] = pvb[it];
            }
            __syncthreads();
        }
        buf ^= 1;
    }

#pragma unroll
    for (int i = 0; i < 8; ++i) {
        int row = m0 + ty * 8 + i;
#pragma unroll
        for (int j4 = 0; j4 < 8; j4 += 4) {
            int col = n0 + tx * 8 + j4;
            float4 r;
            r.x = acc[i][j4 + 0] + bias[col + 0];
            r.y = acc[i][j4 + 1] + bias[col + 1];
            r.z = acc[i][j4 + 2] + bias[col + 2];
            r.w = acc[i][j4 + 3] + bias[col + 3];
            *(float4*)(C + (size_t)row * N + col) = r;
        }
    }
}

// ---------------------------------------------------------------------------
// Causal multi-head attention, flash-style, log2-domain softmax.
// Grid: (8 q-tiles of 128, 64 batch*head). 128 threads; one thread per query
// row. Q row + O accumulator in registers; K/V tiles (32 rows) in smem read
// with warp-uniform indices (pure broadcast -> conflict free). Per-thread
// online softmax in base-2 (exp2f == single MUFU.EX2); softmax is invariant
// to the base change since 1/sqrt(D)*log2(e) is folded into Q.
// Causal early-exit: jend clamps the inner loops; fully-masked tiles become
// trip-count-0 loops (warp-uniformly for whole warps above the diagonal).
// Reads g_qkv ([B*S,3E]: q|k|v per row), writes g_att ([B*S,E], heads merged).
// ---------------------------------------------------------------------------
__global__ __launch_bounds__(128) void attn_kernel()
{
    const int qt  = blockIdx.x;            // 0..7
    const int bh  = blockIdx.y;            // 0..63
    const int b   = bh >> 4;
    const int h   = bh & 15;
    const int tid = threadIdx.x;
    const int qs  = qt * 128 + tid;        // this thread's query position

    __shared__ float Ks[32][64];
    __shared__ float Vs[32][64];
    __shared__ float Ss[128][33];          // stride 33 -> conflict-free per-thread rows

    // 1/sqrt(64) * log2(e): scores live in the log2 domain
    const float QSCALE = 0.125f * 1.4426950408889634f;

    float q[64], o[64];
    const float* qp = g_qkv + (size_t)(b * S_ + qs) * 3 * E_ + h * D_;
#pragma unroll
    for (int d4 = 0; d4 < 16; ++d4) {
        float4 v = *(const float4*)(qp + 4 * d4);
        q[4 * d4 + 0] = v.x * QSCALE;
        q[4 * d4 + 1] = v.y * QSCALE;
        q[4 * d4 + 2] = v.z * QSCALE;
        q[4 * d4 + 3] = v.w * QSCALE;
        o[4 * d4 + 0] = 0.f; o[4 * d4 + 1] = 0.f;
        o[4 * d4 + 2] = 0.f; o[4 * d4 + 3] = 0.f;
    }

    float m = -3.3e38f, l = 0.f;
    const int nt = (qt + 1) * 4;           // causal: only tiles up to the diagonal

    for (int t = 0; t < nt; ++t) {
        const int kb = t * 32;
        __syncthreads();
#pragma unroll
        for (int it = 0; it < 4; ++it) {   // load 32x64 K and V tiles (float4, coalesced)
            int id = tid + it * 128;
            int r = id >> 4, c = (id & 15) << 2;
            const float* kp = g_qkv + (size_t)(b * S_ + kb + r) * 3 * E_ + E_ + h * D_ + c;
            *(float4*)&Ks[r][c] = *(const float4*)kp;
            *(float4*)&Vs[r][c] = *(const float4*)(kp + E_);
        }
        __syncthreads();

        // number of unmasked keys in this tile for my query row (0..32)
        int jend = qs - kb + 1;
        jend = jend < 0 ? 0 : (jend > 32 ? 32 : jend);

        // scores (log2 domain) for my query row vs unmasked keys
        float smax = -3.3e38f;
        for (int j = 0; j < jend; ++j) {
            const float4* kr = (const float4*)Ks[j];
            float a = 0.f;
#pragma unroll
            for (int d4 = 0; d4 < 16; ++d4) {
                float4 kv = kr[d4];
                a += q[4 * d4 + 0] * kv.x + q[4 * d4 + 1] * kv.y
                   + q[4 * d4 + 2] * kv.z + q[4 * d4 + 3] * kv.w;
            }
            Ss[tid][j] = a;
            smax = fmaxf(smax, a);
        }

        if (jend > 0) {
            // online softmax update (per-thread, base 2)
            float mnew = fmaxf(m, smax);
            float corr = exp2f(m - mnew);      // single MUFU.EX2
            l *= corr;
#pragma unroll
            for (int d = 0; d < 64; ++d) o[d] *= corr;

            for (int j = 0; j < jend; ++j) {
                float p = exp2f(Ss[tid][j] - mnew);
                l += p;
                const float4* vr = (const float4*)Vs[j];
#pragma unroll
                for (int d4 = 0; d4 < 16; ++d4) {
                    float4 vv = vr[d4];
                    o[4 * d4 + 0] += p * vv.x;
                    o[4 * d4 + 1] += p * vv.y;
                    o[4 * d4 + 2] += p * vv.z;
                    o[4 * d4 + 3] += p * vv.w;
                }
            }
            m = mnew;
        }
    }

    const float inv = 1.f / l;
    float* op = g_att + (size_t)(b * S_ + qs) * E_ + h * D_;
#pragma unroll
    for (int d4 = 0; d4 < 16; ++d4) {
        float4 v;
        v.x = o[4 * d4 + 0] * inv;
        v.y = o[4 * d4 + 1] * inv;
        v.z = o[4 * d4 + 2] * inv;
        v.w = o[4 * d4 + 3] * inv;
        *(float4*)(op + 4 * d4) = v;
    }
}

// ---------------------------------------------------------------------------
extern "C" void kernel_launch(void* const* d_in, const int* in_sizes, int n_in,
                              void* d_out, int out_size)
{
    const float* x  = (const float*)d_in[0];
    const float* Wa = (const float*)d_in[1];
    const float* ba = (const float*)d_in[2];
    const float* Wp = (const float*)d_in[3];
    const float* bp = (const float*)d_in[4];
    float* out = (float*)d_out;

    float *qkv = nullptr, *att = nullptr;
    cudaGetSymbolAddress((void**)&qkv, g_qkv);   // query, not a stream op: capture-safe
    cudaGetSymbolAddress((void**)&att, g_att);

    // 1) QKV projection: [4096,1024] @ [1024,3072] + bias
    sgemm_bias<<<dim3(24, 32), 256>>>(x, Wa, ba, qkv, B_ * S_, 3 * E_, E_);
    // 2) causal multi-head attention
    attn_kernel<<<dim3(8, 64), 128>>>();
    // 3) output projection: [4096,1024] @ [1024,1024] + bias
    sgemm_bias<<<dim3(8, 32), 256>>>(att, Wp, bp, out, B_ * S_, E_, E_);
}

// round 11
// speedup vs baseline: 1.5808x; 1.5808x over previous
#include <cuda_runtime.h>
#include <cuda_bf16.h>
#include <math.h>
#include <stdint.h>

#define B_  4
#define S_  1024
#define E_  1024
#define H_  16
#define D_  64
#define MT_ (B_ * S_)   // 4096

// Scratch (static device globals: allocation-guard safe)
__device__ float g_qkv[(size_t)MT_ * 3 * E_];   // [4096, 3072]
__device__ float g_att[(size_t)MT_ * E_];       // [4096, 1024]
__device__ float g_wta[(size_t)3 * E_ * E_];    // W_attn^T  [3072, 1024]
__device__ float g_wtp[(size_t)E_ * E_];        // W_proj^T  [1024, 1024]

// ---------------------------------------------------------------------------
// Weight transpose: W [K, N] row-major -> WT [N, K] row-major. block(32,8).
// ---------------------------------------------------------------------------
__global__ void transpose_kernel(const float* __restrict__ W, float* __restrict__ WT,
                                 int K, int N)
{
    __shared__ float t[32][33];
    const int k0 = blockIdx.x * 32, n0 = blockIdx.y * 32;
    const int tx = threadIdx.x, ty = threadIdx.y;
#pragma unroll
    for (int i = 0; i < 32; i += 8)
        t[ty + i][tx] = W[(size_t)(k0 + ty + i) * N + n0 + tx];
    __syncthreads();
#pragma unroll
    for (int i = 0; i < 32; i += 8)
        WT[(size_t)(n0 + ty + i) * K + k0 + tx] = t[tx][ty + i];
}

// ---------------------------------------------------------------------------
// bf16x3 tensor-core GEMM via mma.sync (m16n8k16, sm_80+ PTX, works on base
// sm_103 target): C[M,N] = A[M,K] @ BT[N,K]^T + bias[N].
// fp32 operands split on the fly into bf16 hi + lo; 3 mma passes accumulate
// Ah*Bh + Ah*Bl + Al*Bh in fp32 (dropped Al*Bl ~ 2^-18 -> rel_err ~1e-5).
// CTA: 128x128 tile, 256 threads = 8 warps (2x4), warp tile 64x32.
// BK=32 (2 k16 substeps). Smem: per slab 4 planes (AH,AL,BH,BL) of
// [2 substeps][128 rows][16 bf16], XOR-swizzled rows; double-buffered.
// Register-prefetch pipeline: load slab s+1 while computing slab s.
// ---------------------------------------------------------------------------
#define SUBSTRIDE 4128            // 4096 + 32: bank-shifts ss=1 vs ss=0
#define PLANE     (2 * SUBSTRIDE) // 8256
#define SLABBYTES (4 * PLANE)     // 33024
#define GEMM_SMEM (2 * SLABBYTES) // 66048

__device__ __forceinline__ uint32_t sw_off(int row, int c) {
    // byte offset inside one [128][16 bf16] substep plane; row stride 32B,
    // b32 column c in 0..7 swizzled by row&7 -> conflict-free LDS/STS
    return (uint32_t)(row * 32 + (((c) ^ (row & 7)) << 2));
}
__device__ __forceinline__ uint32_t pack_bf2(__nv_bfloat16 a, __nv_bfloat16 b) {
    __nv_bfloat162 t(a, b);   // .x = low 16 bits
    return *reinterpret_cast<uint32_t*>(&t);
}
// split one float4 into bf16 hi/lo pairs and store (swizzled) to both planes
__device__ __forceinline__ void split_store(char* ph, char* pl, int r, int c, float4 v) {
    __nv_bfloat16 hx = __float2bfloat16(v.x), hy = __float2bfloat16(v.y);
    __nv_bfloat16 hz = __float2bfloat16(v.z), hw = __float2bfloat16(v.w);
    float lx = v.x - __bfloat162float(hx), ly = v.y - __bfloat162float(hy);
    float lz = v.z - __bfloat162float(hz), lw = v.w - __bfloat162float(hw);
    *(uint32_t*)(ph + sw_off(r, c))     = pack_bf2(hx, hy);
    *(uint32_t*)(ph + sw_off(r, c + 1)) = pack_bf2(hz, hw);
    *(uint32_t*)(pl + sw_off(r, c))     = pack_bf2(__float2bfloat16(lx), __float2bfloat16(ly));
    *(uint32_t*)(pl + sw_off(r, c + 1)) = pack_bf2(__float2bfloat16(lz), __float2bfloat16(lw));
}
#define MMA16816(d, a, b) \
    asm volatile("mma.sync.aligned.m16n8k16.row.col.f32.bf16.bf16.f32 " \
                 "{%0,%1,%2,%3}, {%4,%5,%6,%7}, {%8,%9}, {%0,%1,%2,%3};" \
                 : "+f"((d)[0]), "+f"((d)[1]), "+f"((d)[2]), "+f"((d)[3]) \
                 : "r"((a)[0]), "r"((a)[1]), "r"((a)[2]), "r"((a)[3]), \
                   "r"((b)[0]), "r"((b)[1]))

__global__ __launch_bounds__(256) void gemm_mma(
    const float* __restrict__ A, const float* __restrict__ BT,
    const float* __restrict__ bias, float* __restrict__ C,
    int M, int N, int K)
{
    extern __shared__ char smem[];
    const int tid  = threadIdx.x;
    const int wid  = tid >> 5, lane = tid & 31;
    const int wm   = (wid >> 2) * 64;   // warp m offset: 0 or 64
    const int wn   = (wid & 3) * 32;    // warp n offset: 0,32,64,96
    const int g    = lane >> 2, tig = lane & 3;
    const int m0   = blockIdx.y * 128, n0 = blockIdx.x * 128;

    float acc[4][4][4];
#pragma unroll
    for (int mi = 0; mi < 4; ++mi)
#pragma unroll
        for (int nj = 0; nj < 4; ++nj)
#pragma unroll
            for (int k = 0; k < 4; ++k) acc[mi][nj][k] = 0.f;

    const int nslab = K / 32;
    float4 pa[4], pb[4];

    // prologue: load slab 0
#pragma unroll
    for (int i = 0; i < 4; ++i) {
        int idx = tid + (i << 8);
        int r = idx >> 3, k4 = idx & 7;
        pa[i] = *(const float4*)(A  + (size_t)(m0 + r) * K + (k4 << 2));
        pb[i] = *(const float4*)(BT + (size_t)(n0 + r) * K + (k4 << 2));
    }
    {   // store slab 0 -> buffer 0
        char* dst = smem;
#pragma unroll
        for (int i = 0; i < 4; ++i) {
            int idx = tid + (i << 8);
            int r = idx >> 3, k4 = idx & 7;
            int ss = k4 >> 2, c = (k4 & 3) << 1;
            char* base = dst + ss * SUBSTRIDE;
            split_store(base + 0 * PLANE, base + 1 * PLANE, r, c, pa[i]);   // AH, AL
            split_store(base + 2 * PLANE, base + 3 * PLANE, r, c, pb[i]);   // BH, BL
        }
    }
    __syncthreads();

    for (int s = 0; s < nslab; ++s) {
        char* buf = smem + (s & 1) * SLABBYTES;
        const bool more = (s + 1) < nslab;
        if (more) {                      // prefetch next slab into registers
            const int ko = (s + 1) * 32;
#pragma unroll
            for (int i = 0; i < 4; ++i) {
                int idx = tid + (i << 8);
                int r = idx >> 3, k4 = idx & 7;
                pa[i] = *(const float4*)(A  + (size_t)(m0 + r) * K + ko + (k4 << 2));
                pb[i] = *(const float4*)(BT + (size_t)(n0 + r) * K + ko + (k4 << 2));
            }
        }

#pragma unroll
        for (int ss = 0; ss < 2; ++ss) {
            const char* pAH = buf + 0 * PLANE + ss * SUBSTRIDE;
            const char* pAL = buf + 1 * PLANE + ss * SUBSTRIDE;
            const char* pBH = buf + 2 * PLANE + ss * SUBSTRIDE;
            const char* pBL = buf + 3 * PLANE + ss * SUBSTRIDE;
            uint32_t a[4][4], bh[4][2], bl[4][2];
#pragma unroll
            for (int mi = 0; mi < 4; ++mi) {
                int R = wm + mi * 16 + g;
                a[mi][0] = *(const uint32_t*)(pAH + sw_off(R,     tig));
                a[mi][1] = *(const uint32_t*)(pAH + sw_off(R + 8, tig));
                a[mi][2] = *(const uint32_t*)(pAH + sw_off(R,     tig + 4));
                a[mi][3] = *(const uint32_t*)(pAH + sw_off(R + 8, tig + 4));
            }
#pragma unroll
            for (int nj = 0; nj < 4; ++nj) {
                int Rn = wn + nj * 8 + g;
                bh[nj][0] = *(const uint32_t*)(pBH + sw_off(Rn, tig));
                bh[nj][1] = *(const uint32_t*)(pBH + sw_off(Rn, tig + 4));
                bl[nj][0] = *(const uint32_t*)(pBL + sw_off(Rn, tig));
                bl[nj][1] = *(const uint32_t*)(pBL + sw_off(Rn, tig + 4));
            }
#pragma unroll
            for (int mi = 0; mi < 4; ++mi)
#pragma unroll
                for (int nj = 0; nj < 4; ++nj) {
                    MMA16816(acc[mi][nj], a[mi], bh[nj]);   // Ah*Bh
                    MMA16816(acc[mi][nj], a[mi], bl[nj]);   // Ah*Bl
                }
#pragma unroll
            for (int mi = 0; mi < 4; ++mi) {                // reload a <- Al
                int R = wm + mi * 16 + g;
                a[mi][0] = *(const uint32_t*)(pAL + sw_off(R,     tig));
                a[mi][1] = *(const uint32_t*)(pAL + sw_off(R + 8, tig));
                a[mi][2] = *(const uint32_t*)(pAL + sw_off(R,     tig + 4));
                a[mi][3] = *(const uint32_t*)(pAL + sw_off(R + 8, tig + 4));
            }
#pragma unroll
            for (int mi = 0; mi < 4; ++mi)
#pragma unroll
                for (int nj = 0; nj < 4; ++nj)
                    MMA16816(acc[mi][nj], a[mi], bh[nj]);   // Al*Bh
        }

        if (more) {                      // drain prefetch into the other buffer
            char* dst = smem + ((s + 1) & 1) * SLABBYTES;
#pragma unroll
            for (int i = 0; i < 4; ++i) {
                int idx = tid + (i << 8);
                int r = idx >> 3, k4 = idx & 7;
                int ss = k4 >> 2, c = (k4 & 3) << 1;
                char* base = dst + ss * SUBSTRIDE;
                split_store(base + 0 * PLANE, base + 1 * PLANE, r, c, pa[i]);
                split_store(base + 2 * PLANE, base + 3 * PLANE, r, c, pb[i]);
            }
        }
        __syncthreads();
    }

    // epilogue: acc -> C (+bias). c0:(R+g, col) c1:(col+1) c2:(R+g+8, col) c3:(col+1)
#pragma unroll
    for (int mi = 0; mi < 4; ++mi) {
        int row = m0 + wm + mi * 16 + g;
#pragma unroll
        for (int nj = 0; nj < 4; ++nj) {
            int col = n0 + wn + nj * 8 + 2 * tig;
            float b0 = bias[col], b1 = bias[col + 1];
            float2 v0 = make_float2(acc[mi][nj][0] + b0, acc[mi][nj][1] + b1);
            float2 v1 = make_float2(acc[mi][nj][2] + b0, acc[mi][nj][3] + b1);
            *(float2*)(C + (size_t)row * N + col)       = v0;
            *(float2*)(C + (size_t)(row + 8) * N + col) = v1;
        }
    }
}

// ---------------------------------------------------------------------------
// Causal multi-head attention, flash-style, log2-domain softmax (unchanged).
// ---------------------------------------------------------------------------
__global__ __launch_bounds__(128) void attn_kernel()
{
    const int qt  = blockIdx.x;
    const int bh  = blockIdx.y;
    const int b   = bh >> 4;
    const int h   = bh & 15;
    const int tid = threadIdx.x;
    const int qs  = qt * 128 + tid;

    __shared__ float Ks[32][64];
    __shared__ float Vs[32][64];
    __shared__ float Ss[128][33];

    const float QSCALE = 0.125f * 1.4426950408889634f;

    float q[64], o[64];
    const float* qp = g_qkv + (size_t)(b * S_ + qs) * 3 * E_ + h * D_;
#pragma unroll
    for (int d4 = 0; d4 < 16; ++d4) {
        float4 v = *(const float4*)(qp + 4 * d4);
        q[4 * d4 + 0] = v.x * QSCALE;
        q[4 * d4 + 1] = v.y * QSCALE;
        q[4 * d4 + 2] = v.z * QSCALE;
        q[4 * d4 + 3] = v.w * QSCALE;
        o[4 * d4 + 0] = 0.f; o[4 * d4 + 1] = 0.f;
        o[4 * d4 + 2] = 0.f; o[4 * d4 + 3] = 0.f;
    }

    float m = -3.3e38f, l = 0.f;
    const int nt = (qt + 1) * 4;

    for (int t = 0; t < nt; ++t) {
        const int kb = t * 32;
        __syncthreads();
#pragma unroll
        for (int it = 0; it < 4; ++it) {
            int id = tid + it * 128;
            int r = id >> 4, c = (id & 15) << 2;
            const float* kp = g_qkv + (size_t)(b * S_ + kb + r) * 3 * E_ + E_ + h * D_ + c;
            *(float4*)&Ks[r][c] = *(const float4*)kp;
            *(float4*)&Vs[r][c] = *(const float4*)(kp + E_);
        }
        __syncthreads();

        int jend = qs - kb + 1;
        jend = jend < 0 ? 0 : (jend > 32 ? 32 : jend);

        float smax = -3.3e38f;
        for (int j = 0; j < jend; ++j) {
            const float4* kr = (const float4*)Ks[j];
            float a = 0.f;
#pragma unroll
            for (int d4 = 0; d4 < 16; ++d4) {
                float4 kv = kr[d4];
                a += q[4 * d4 + 0] * kv.x + q[4 * d4 + 1] * kv.y
                   + q[4 * d4 + 2] * kv.z + q[4 * d4 + 3] * kv.w;
            }
            Ss[tid][j] = a;
            smax = fmaxf(smax, a);
        }

        if (jend > 0) {
            float mnew = fmaxf(m, smax);
            float corr = exp2f(m - mnew);
            l *= corr;
#pragma unroll
            for (int d = 0; d < 64; ++d) o[d] *= corr;

            for (int j = 0; j < jend; ++j) {
                float p = exp2f(Ss[tid][j] - mnew);
                l += p;
                const float4* vr = (const float4*)Vs[j];
#pragma unroll
                for (int d4 = 0; d4 < 16; ++d4) {
                    float4 vv = vr[d4];
                    o[4 * d4 + 0] += p * vv.x;
                    o[4 * d4 + 1] += p * vv.y;
                    o[4 * d4 + 2] += p * vv.z;
                    o[4 * d4 + 3] += p * vv.w;
                }
            }
            m = mnew;
        }
    }

    const float inv = 1.f / l;
    float* op = g_att + (size_t)(b * S_ + qs) * E_ + h * D_;
#pragma unroll
    for (int d4 = 0; d4 < 16; ++d4) {
        float4 v;
        v.x = o[4 * d4 + 0] * inv;
        v.y = o[4 * d4 + 1] * inv;
        v.z = o[4 * d4 + 2] * inv;
        v.w = o[4 * d4 + 3] * inv;
        *(float4*)(op + 4 * d4) = v;
    }
}

// ---------------------------------------------------------------------------
extern "C" void kernel_launch(void* const* d_in, const int* in_sizes, int n_in,
                              void* d_out, int out_size)
{
    const float* x  = (const float*)d_in[0];
    const float* Wa = (const float*)d_in[1];
    const float* ba = (const float*)d_in[2];
    const float* Wp = (const float*)d_in[3];
    const float* bp = (const float*)d_in[4];
    float* out = (float*)d_out;

    float *qkv = nullptr, *att = nullptr, *wta = nullptr, *wtp = nullptr;
    cudaGetSymbolAddress((void**)&qkv, g_qkv);
    cudaGetSymbolAddress((void**)&att, g_att);
    cudaGetSymbolAddress((void**)&wta, g_wta);
    cudaGetSymbolAddress((void**)&wtp, g_wtp);

    cudaFuncSetAttribute(gemm_mma, cudaFuncAttributeMaxDynamicSharedMemorySize, GEMM_SMEM);

    // 0) transpose weights: W[K,N] -> WT[N,K]
    transpose_kernel<<<dim3(32, 96), dim3(32, 8)>>>(Wa, wta, E_, 3 * E_);
    transpose_kernel<<<dim3(32, 32), dim3(32, 8)>>>(Wp, wtp, E_, E_);

    // 1) QKV projection: [4096,1024] @ [1024,3072] + bias (bf16x3 mma.sync)
    gemm_mma<<<dim3(24, 32), 256, GEMM_SMEM>>>(x, wta, ba, qkv, MT_, 3 * E_, E_);
    // 2) causal multi-head attention
    attn_kernel<<<dim3(8, 64), 128>>>();
    // 3) output projection: [4096,1024] @ [1024,1024] + bias
    gemm_mma<<<dim3(8, 32), 256, GEMM_SMEM>>>(att, wtp, bp, out, MT_, E_, E_);
}